// round 16
// baseline (speedup 1.0000x reference)
#include <cuda_runtime.h>
#include <cuda_fp16.h>
#include <mma.h>
#include <math.h>
#include <cstdint>

using namespace nvcuda;

#define N_NODES 20000
#define E_EDGES 640000
#define TOT_E   (E_EDGES + N_NODES)
#define NGRAPH  64
#define OUTF    10
#define NEG_SLOPE 0.2f
#define XE  (N_NODES * 256)
#define W1E (256 * 256)
#define W2E (128 * 256)
#define CVT_TOTAL (XE + W1E + W2E)
#define CVT4 ((CVT_TOTAL + 3) / 4)

__device__ __align__(16) __half g_xh   [(size_t)N_NODES * 256];
__device__ __align__(16) __half g_w1h  [W1E];
__device__ __align__(16) __half g_w2h  [W2E];
__device__ __align__(16) __half g_h1   [(size_t)N_NODES * 256];
__device__ __align__(16) __half g_out1h[(size_t)N_NODES * 256];
__device__ __align__(16) __half g_h2   [(size_t)N_NODES * 128];
__device__ __align__(16) float  g_out2 [(size_t)N_NODES * 128];
__device__ float g_al_s1[N_NODES * 2];
__device__ float g_al_d1[N_NODES * 2];
__device__ float g_al_s2[N_NODES];
__device__ float g_al_d2[N_NODES];
__device__ int g_deg[N_NODES];
__device__ int g_off[N_NODES + 1];
__device__ int g_csr_src[TOT_E];
__device__ int g_ei[2 * E_EDGES];
__device__ int g_rank[E_EDGES];
__device__ int g_batch[N_NODES];

__device__ __forceinline__ int detect64(const int* raw_e, int* s_flag) {
    if (threadIdx.x == 0) {
        int any = 0;
        for (int i = 0; i < 256; i++) any |= raw_e[2 * i + 1];
        *s_flag = (any == 0) ? 1 : 0;
    }
    __syncthreads();
    return *s_flag;
}

// merged: batch convert + edge convert/count/rank + fp32->fp16 conversion.
// g_deg is zeroed by cudaMemsetAsync BEFORE this kernel (stream-ordered).
__global__ void prep_all_kernel(const int* raw_e, const int* raw_b,
                                const float* x, const float* W1, const float* W2) {
    __shared__ int s_flag;
    int is64 = detect64(raw_e, &s_flag);
    int gi = blockIdx.x * blockDim.x + threadIdx.x;

    if (gi < N_NODES)
        g_batch[gi] = is64 ? raw_b[2 * gi] : raw_b[gi];

    if (gi < E_EDGES) {
        int es = is64 ? raw_e[2 * gi] : raw_e[gi];
        int ed = is64 ? raw_e[2 * (E_EDGES + gi)] : raw_e[E_EDGES + gi];
        g_ei[gi] = es;
        g_ei[E_EDGES + gi] = ed;
        g_rank[gi] = atomicAdd(&g_deg[ed], 1);
    }

    if (gi < CVT4) {
        int idx4 = gi * 4;
        const float* src;
        __half* dst;
        int off;
        if (idx4 < XE) { src = x; dst = g_xh; off = idx4; }
        else if (idx4 < XE + W1E) { src = W1; dst = g_w1h; off = idx4 - XE; }
        else { src = W2; dst = g_w2h; off = idx4 - XE - W1E; }
        float4 fv = *reinterpret_cast<const float4*>(src + off);
        __half2 h0 = __floats2half2_rn(fv.x, fv.y);
        __half2 h1 = __floats2half2_rn(fv.z, fv.w);
        uint2 pk;
        pk.x = *reinterpret_cast<unsigned int*>(&h0);
        pk.y = *reinterpret_cast<unsigned int*>(&h1);
        *reinterpret_cast<uint2*>(dst + off) = pk;
    }
}

// coalesced warp-scan: 32 warps x 640-element contiguous segments.
__global__ void scan_kernel() {
    __shared__ int wtot[32];
    __shared__ int woff[32];
    int lane = threadIdx.x & 31;
    int w = threadIdx.x >> 5;
    int base = w * 640;

    int sum = 0;
    for (int k = 0; k < 20; k++) {
        int e = base + k * 32 + lane;
        sum += (e < N_NODES) ? (g_deg[e] + 1) : 0;
    }
    for (int o = 16; o; o >>= 1) sum += __shfl_xor_sync(0xffffffffu, sum, o);
    if (lane == 0) wtot[w] = sum;
    __syncthreads();

    if (w == 0) {
        int v = wtot[lane];
        int s = v;
        for (int o = 1; o < 32; o <<= 1) {
            int t = __shfl_up_sync(0xffffffffu, s, o);
            if (lane >= o) s += t;
        }
        woff[lane] = s - v;
    }
    __syncthreads();

    int carry = woff[w];
    for (int k = 0; k < 20; k++) {
        int e = base + k * 32 + lane;
        int v = (e < N_NODES) ? (g_deg[e] + 1) : 0;
        int s = v;
        for (int o = 1; o < 32; o <<= 1) {
            int t = __shfl_up_sync(0xffffffffu, s, o);
            if (lane >= o) s += t;
        }
        if (e < N_NODES) g_off[e] = carry + s - v;
        carry += __shfl_sync(0xffffffffu, s, 31);
    }
    if (threadIdx.x == 0) g_off[N_NODES] = TOT_E;
}

__global__ void fill_kernel() {
    int i = blockIdx.x * blockDim.x + threadIdx.x;
    if (i < E_EDGES) {
        g_csr_src[g_off[g_ei[E_EDGES + i]] + g_rank[i]] = g_ei[i];
    } else if (i < TOT_E) {
        int n = i - E_EDGES;
        g_csr_src[g_off[n] + g_deg[n]] = n;
    }
}

// WMMA GEMM with DOUBLE-BUFFERED smem tiles: one __syncthreads per k-step.
// C_half[M x NC] = fp16(A_half[M x 256] @ B_half[NC x 256]^T), fp32 accum.
// Block 128x128, 8 warps (2M x 4N), warp tile 64x32, BK=16.
template <int NC>
__device__ __forceinline__ void wmma_gemm_body(const __half* A, const __half* B,
                                               __half* C, int M) {
    const int K = 256;
    const int LDS_PAD = 24;
    __shared__ __align__(16) __half Am[2][128 * LDS_PAD];
    __shared__ __align__(16) __half Bm[2][128 * LDS_PAD];
    __shared__ __align__(16) float Cp[8][16 * 16];

    int tid = threadIdx.x;
    int lane = tid & 31;
    int wid = tid >> 5;
    int wm = wid & 1;
    int wn = wid >> 1;
    int bm = blockIdx.x * 128;
    int bn = blockIdx.y * 128;

    int lrow = tid >> 1;
    int lpart = (tid & 1) * 8;
    bool arow_ok = (bm + lrow) < M;
    const __half* aptr = A + (size_t)(bm + lrow) * K + lpart;
    const __half* bptr = B + (size_t)(bn + lrow) * K + lpart;
    __half* As_dst0 = Am[0] + lrow * LDS_PAD + lpart;
    __half* As_dst1 = Am[1] + lrow * LDS_PAD + lpart;
    __half* Bs_dst0 = Bm[0] + lrow * LDS_PAD + lpart;
    __half* Bs_dst1 = Bm[1] + lrow * LDS_PAD + lpart;

    wmma::fragment<wmma::matrix_a, 16, 16, 16, __half, wmma::row_major> af[4];
    wmma::fragment<wmma::matrix_b, 16, 16, 16, __half, wmma::col_major> bf[2];
    wmma::fragment<wmma::accumulator, 16, 16, 16, float> cf[4][2];
#pragma unroll
    for (int mt = 0; mt < 4; mt++)
#pragma unroll
        for (int nt = 0; nt < 2; nt++) wmma::fill_fragment(cf[mt][nt], 0.f);

    uint4 z4 = make_uint4(0, 0, 0, 0);

    // prologue: tile 0 into buffer 0
    {
        uint4 ra = arow_ok ? *reinterpret_cast<const uint4*>(aptr) : z4;
        uint4 rb = *reinterpret_cast<const uint4*>(bptr);
        *reinterpret_cast<uint4*>(As_dst0) = ra;
        *reinterpret_cast<uint4*>(Bs_dst0) = rb;
    }
    __syncthreads();

#pragma unroll
    for (int step = 0; step < K / 16; step++) {
        int cur = step & 1;
        bool has_next = (step + 1) < (K / 16);
        uint4 ra = z4;
        uint4 rb = z4;
        if (has_next) {
            int kn = (step + 1) * 16;
            if (arow_ok) ra = *reinterpret_cast<const uint4*>(aptr + kn);
            rb = *reinterpret_cast<const uint4*>(bptr + kn);
        }
        const __half* Asrc = Am[cur];
        const __half* Bsrc = Bm[cur];
#pragma unroll
        for (int mt = 0; mt < 4; mt++)
            wmma::load_matrix_sync(af[mt], Asrc + (wm * 64 + mt * 16) * LDS_PAD, LDS_PAD);
#pragma unroll
        for (int nt = 0; nt < 2; nt++)
            wmma::load_matrix_sync(bf[nt], Bsrc + (wn * 32 + nt * 16) * LDS_PAD, LDS_PAD);
#pragma unroll
        for (int mt = 0; mt < 4; mt++)
#pragma unroll
            for (int nt = 0; nt < 2; nt++)
                wmma::mma_sync(cf[mt][nt], af[mt], bf[nt], cf[mt][nt]);
        if (has_next) {
            if (cur == 0) {
                *reinterpret_cast<uint4*>(As_dst1) = ra;
                *reinterpret_cast<uint4*>(Bs_dst1) = rb;
            } else {
                *reinterpret_cast<uint4*>(As_dst0) = ra;
                *reinterpret_cast<uint4*>(Bs_dst0) = rb;
            }
            __syncthreads();
        }
    }

#pragma unroll
    for (int mt = 0; mt < 4; mt++) {
#pragma unroll
        for (int nt = 0; nt < 2; nt++) {
            wmma::store_matrix_sync(Cp[wid], cf[mt][nt], 16, wmma::mem_row_major);
            __syncwarp();
            int idx = lane * 8;
            int rr = idx >> 4;
            int cc = idx & 15;
            const float* pp = Cp[wid] + rr * 16 + cc;
            __half2 hv[4];
            hv[0] = __floats2half2_rn(pp[0], pp[1]);
            hv[1] = __floats2half2_rn(pp[2], pp[3]);
            hv[2] = __floats2half2_rn(pp[4], pp[5]);
            hv[3] = __floats2half2_rn(pp[6], pp[7]);
            int grow = bm + wm * 64 + mt * 16 + rr;
            int gcol = bn + wn * 32 + nt * 16 + cc;
            if (grow < M)
                *reinterpret_cast<uint4*>(C + (size_t)grow * NC + gcol) =
                    *reinterpret_cast<const uint4*>(hv);
            __syncwarp();
        }
    }
}

__global__ __launch_bounds__(256, 2) void gemm1_kernel() {
    wmma_gemm_body<256>(g_xh, g_w1h, g_h1, N_NODES);
}
__global__ __launch_bounds__(256, 2) void gemm2_kernel() {
    wmma_gemm_body<128>(g_out1h, g_w2h, g_h2, N_NODES);
}

__global__ void logits1_kernel(const float* a_s, const float* a_d) {
    int w = (blockIdx.x * blockDim.x + threadIdx.x) >> 5;
    int lane = threadIdx.x & 31;
    if (w >= N_NODES * 2) return;
    int n = w >> 1;
    int h = w & 1;
    const __half* hp = g_h1 + (size_t)n * 256 + h * 128 + lane * 4;
    uint2 raw = *reinterpret_cast<const uint2*>(hp);
    const __half2* h2p = reinterpret_cast<const __half2*>(&raw);
    float2 f0 = __half22float2(h2p[0]);
    float2 f1 = __half22float2(h2p[1]);
    int c = h * 128 + lane * 4;
    float ss = f0.x * a_s[c] + f0.y * a_s[c + 1] + f1.x * a_s[c + 2] + f1.y * a_s[c + 3];
    float sd = f0.x * a_d[c] + f0.y * a_d[c + 1] + f1.x * a_d[c + 2] + f1.y * a_d[c + 3];
    for (int o = 16; o; o >>= 1) {
        ss += __shfl_xor_sync(0xffffffffu, ss, o);
        sd += __shfl_xor_sync(0xffffffffu, sd, o);
    }
    if (lane == 0) {
        g_al_s1[n * 2 + h] = ss;
        g_al_d1[n * 2 + h] = sd;
    }
}

__global__ void logits2_kernel(const float* a_s, const float* a_d) {
    int w = (blockIdx.x * blockDim.x + threadIdx.x) >> 5;
    int lane = threadIdx.x & 31;
    if (w >= N_NODES) return;
    const __half* hp = g_h2 + (size_t)w * 128 + lane * 4;
    uint2 raw = *reinterpret_cast<const uint2*>(hp);
    const __half2* h2p = reinterpret_cast<const __half2*>(&raw);
    float2 f0 = __half22float2(h2p[0]);
    float2 f1 = __half22float2(h2p[1]);
    int c = lane * 4;
    float ss = f0.x * a_s[c] + f0.y * a_s[c + 1] + f1.x * a_s[c + 2] + f1.y * a_s[c + 3];
    float sd = f0.x * a_d[c] + f0.y * a_d[c + 1] + f1.x * a_d[c + 2] + f1.y * a_d[c + 3];
    for (int o = 16; o; o >>= 1) {
        ss += __shfl_xor_sync(0xffffffffu, ss, o);
        sd += __shfl_xor_sync(0xffffffffu, sd, o);
    }
    if (lane == 0) {
        g_al_s2[w] = ss;
        g_al_d2[w] = sd;
    }
}

// agg1: warp per node, both heads; next-chunk CSR prefetch overlaps gathers.
__global__ void agg1_kernel(const float* b1) {
    int w = (blockIdx.x * blockDim.x + threadIdx.x) >> 5;
    int lane = threadIdx.x & 31;
    if (w >= N_NODES) return;
    int beg = g_off[w];
    int end = g_off[w + 1];
    float2 ald = *reinterpret_cast<const float2*>(&g_al_d1[w * 2]);

    float den0 = 0.f;
    float den1 = 0.f;
    float acc[8];
#pragma unroll
    for (int k = 0; k < 8; k++) acc[k] = 0.f;

    int s = (beg + lane < end) ? g_csr_src[beg + lane] : 0;
    for (int cbeg = beg; cbeg < end; cbeg += 32) {
        int i = cbeg + lane;
        float ex0 = 0.f;
        float ex1 = 0.f;
        if (i < end) {
            float2 als = *reinterpret_cast<const float2*>(&g_al_s1[s * 2]);
            float e0 = als.x + ald.x;
            float e1 = als.y + ald.y;
            e0 = (e0 > 0.f) ? e0 : e0 * NEG_SLOPE;
            e1 = (e1 > 0.f) ? e1 : e1 * NEG_SLOPE;
            ex0 = __expf(e0);
            ex1 = __expf(e1);
        }
        den0 += ex0;
        den1 += ex1;
        int nchunk = cbeg + 32;
        int s_next = (nchunk + lane < end) ? g_csr_src[nchunk + lane] : 0;
        int cnt = min(32, end - cbeg);
        int j = 0;
        for (; j + 8 <= cnt; j += 8) {
#pragma unroll
            for (int u = 0; u < 8; u++) {
                int sj = __shfl_sync(0xffffffffu, s, j + u);
                float x0 = __shfl_sync(0xffffffffu, ex0, j + u);
                float x1 = __shfl_sync(0xffffffffu, ex1, j + u);
                float xw = (lane < 16) ? x0 : x1;
                float4 raw = reinterpret_cast<const float4*>(g_h1 + (size_t)sj * 256)[lane];
                const __half2* hp = reinterpret_cast<const __half2*>(&raw);
#pragma unroll
                for (int q = 0; q < 4; q++) {
                    float2 f = __half22float2(hp[q]);
                    acc[2 * q] += xw * f.x;
                    acc[2 * q + 1] += xw * f.y;
                }
            }
        }
        for (; j < cnt; j++) {
            int sj = __shfl_sync(0xffffffffu, s, j);
            float x0 = __shfl_sync(0xffffffffu, ex0, j);
            float x1 = __shfl_sync(0xffffffffu, ex1, j);
            float xw = (lane < 16) ? x0 : x1;
            float4 raw = reinterpret_cast<const float4*>(g_h1 + (size_t)sj * 256)[lane];
            const __half2* hp = reinterpret_cast<const __half2*>(&raw);
#pragma unroll
            for (int q = 0; q < 4; q++) {
                float2 f = __half22float2(hp[q]);
                acc[2 * q] += xw * f.x;
                acc[2 * q + 1] += xw * f.y;
            }
        }
        s = s_next;
    }
#pragma unroll
    for (int o = 16; o; o >>= 1) {
        den0 += __shfl_xor_sync(0xffffffffu, den0, o);
        den1 += __shfl_xor_sync(0xffffffffu, den1, o);
    }
    float inv = (lane < 16) ? (1.0f / den0) : (1.0f / den1);
    __half2 hv[4];
#pragma unroll
    for (int q = 0; q < 4; q++) {
        float c0 = fmaxf(acc[2 * q] * inv + b1[lane * 8 + 2 * q], 0.f);
        float c1 = fmaxf(acc[2 * q + 1] * inv + b1[lane * 8 + 2 * q + 1], 0.f);
        hv[q] = __floats2half2_rn(c0, c1);
    }
    *reinterpret_cast<uint4*>(g_out1h + (size_t)w * 256 + lane * 8) =
        *reinterpret_cast<const uint4*>(hv);
}

__global__ void agg2_kernel(const float* b2) {
    int w = (blockIdx.x * blockDim.x + threadIdx.x) >> 5;
    int lane = threadIdx.x & 31;
    if (w >= N_NODES) return;
    int beg = g_off[w];
    int end = g_off[w + 1];
    float ald = g_al_d2[w];

    float den = 0.f;
    float4 acc = make_float4(0.f, 0.f, 0.f, 0.f);
    int s = (beg + lane < end) ? g_csr_src[beg + lane] : 0;
    for (int cbeg = beg; cbeg < end; cbeg += 32) {
        int i = cbeg + lane;
        float ex = 0.f;
        if (i < end) {
            float e = g_al_s2[s] + ald;
            e = (e > 0.f) ? e : e * NEG_SLOPE;
            ex = __expf(e);
        }
        den += ex;
        int nchunk = cbeg + 32;
        int s_next = (nchunk + lane < end) ? g_csr_src[nchunk + lane] : 0;
        int cnt = min(32, end - cbeg);
        int j = 0;
        for (; j + 8 <= cnt; j += 8) {
#pragma unroll
            for (int u = 0; u < 8; u++) {
                int sj = __shfl_sync(0xffffffffu, s, j + u);
                float xv = __shfl_sync(0xffffffffu, ex, j + u);
                float2 raw = reinterpret_cast<const float2*>(g_h2 + (size_t)sj * 128)[lane];
                const __half2* hp = reinterpret_cast<const __half2*>(&raw);
                float2 f0 = __half22float2(hp[0]);
                float2 f1 = __half22float2(hp[1]);
                acc.x += xv * f0.x;
                acc.y += xv * f0.y;
                acc.z += xv * f1.x;
                acc.w += xv * f1.y;
            }
        }
        for (; j < cnt; j++) {
            int sj = __shfl_sync(0xffffffffu, s, j);
            float xv = __shfl_sync(0xffffffffu, ex, j);
            float2 raw = reinterpret_cast<const float2*>(g_h2 + (size_t)sj * 128)[lane];
            const __half2* hp = reinterpret_cast<const __half2*>(&raw);
            float2 f0 = __half22float2(hp[0]);
            float2 f1 = __half22float2(hp[1]);
            acc.x += xv * f0.x;
            acc.y += xv * f0.y;
            acc.z += xv * f1.x;
            acc.w += xv * f1.y;
        }
        s = s_next;
    }
#pragma unroll
    for (int o = 16; o; o >>= 1) den += __shfl_xor_sync(0xffffffffu, den, o);
    float inv = 1.0f / den;
    float4 bv = reinterpret_cast<const float4*>(b2)[lane];
    float4 ov = make_float4(acc.x * inv + bv.x, acc.y * inv + bv.y,
                            acc.z * inv + bv.z, acc.w * inv + bv.w);
    reinterpret_cast<float4*>(g_out2 + (size_t)w * 128)[lane] = ov;
}

__device__ __forceinline__ int lbound(const int* a, int n, int key) {
    int lo = 0;
    int hi = n;
    while (lo < hi) {
        int mid = (lo + hi) >> 1;
        if (a[mid] < key) lo = mid + 1; else hi = mid;
    }
    return lo;
}

__global__ void pool_head_kernel(const float* Wp, const float* bp, float* out) {
    int g = blockIdx.x;
    __shared__ int s_beg;
    __shared__ int s_end;
    __shared__ float mean[128];
    if (threadIdx.x == 0) {
        s_beg = lbound(g_batch, N_NODES, g);
        s_end = lbound(g_batch, N_NODES, g + 1);
    }
    __syncthreads();
    int c = threadIdx.x;
    float acc = 0.f;
    for (int n = s_beg; n < s_end; n++) acc += g_out2[(size_t)n * 128 + c];
    float cnt = (float)max(s_end - s_beg, 1);
    mean[c] = acc / cnt;
    __syncthreads();
    if (c < OUTF) {
        float s = bp[c];
        const float* wr = Wp + c * 128;
        for (int k = 0; k < 128; k++) s += mean[k] * wr[k];
        out[g * OUTF + c] = s;
    }
}

extern "C" void kernel_launch(void* const* d_in, const int* in_sizes, int n_in,
                              void* d_out, int out_size) {
    const float* x      = (const float*)d_in[0];
    const int*   ei_raw = (const int*)d_in[1];
    const int*   b_raw  = (const int*)d_in[2];
    const float* W1     = (const float*)d_in[3];
    const float* a_src1 = (const float*)d_in[4];
    const float* a_dst1 = (const float*)d_in[5];
    const float* b1     = (const float*)d_in[6];
    const float* W2     = (const float*)d_in[7];
    const float* a_src2 = (const float*)d_in[8];
    const float* a_dst2 = (const float*)d_in[9];
    const float* b2     = (const float*)d_in[10];
    const float* Wp     = (const float*)d_in[11];
    const float* bp     = (const float*)d_in[12];
    float*       out    = (float*)d_out;

    void* degp = 0;
    cudaGetSymbolAddress(&degp, g_deg);
    cudaMemsetAsync(degp, 0, N_NODES * sizeof(int));

    prep_all_kernel<<<(CVT4 + 255) / 256, 256>>>(ei_raw, b_raw, x, W1, W2);
    scan_kernel<<<1, 1024>>>();
    fill_kernel<<<(TOT_E + 255) / 256, 256>>>();

    gemm1_kernel<<<dim3((N_NODES + 127) / 128, 2), 256>>>();
    logits1_kernel<<<(N_NODES * 2 * 32 + 255) / 256, 256>>>(a_src1, a_dst1);
    agg1_kernel<<<(N_NODES * 32 + 255) / 256, 256>>>(b1);

    gemm2_kernel<<<dim3((N_NODES + 127) / 128, 1), 256>>>();
    logits2_kernel<<<(N_NODES * 32 + 255) / 256, 256>>>(a_src2, a_dst2);
    agg2_kernel<<<(N_NODES * 32 + 255) / 256, 256>>>(b2);

    pool_head_kernel<<<NGRAPH, 128>>>(Wp, bp, out);
}